// round 17
// baseline (speedup 1.0000x reference)
#include <cuda_runtime.h>
#include <cuda_fp16.h>
#include <math.h>
#include <stdint.h>

// ----------------------------------------------------------------------------
// Problem constants
// ----------------------------------------------------------------------------
#define B   32
#define NK  1024
#define S   16
#define D   768
#define H   8
#define DH  64
#define HD  (H*DH)    // 512
#define QKV3 (3*HD)   // 1536
#define INNER 3072
#define N_STEPS 4
#define MS  (B*S)     // 512
static __device__ __constant__ float kSCALE = 0.036084391824351615f;  // 768^-0.5

// ----------------------------------------------------------------------------
// Scratch (device globals)
// ----------------------------------------------------------------------------
__device__ __half g_xnh[B*NK*D];
__device__ __half g_wkh [D*D];
__device__ __half g_wvh [D*D];
__device__ __half g_wqh [D*D];
__device__ __half g_wqkh[QKV3*D];
__device__ __half g_woh [D*HD];
__device__ __half g_w1h [2*INNER*D];
__device__ __half g_w2h [D*INNER];
__device__ __half g_qnh[MS*D];
__device__ __half g_abh[MS*D];
__device__ __half g_fbh[MS*D];
__device__ __half g_innh[MS*INNER];
__device__ __half g_oah[MS*HD];
__device__ __half g_k  [B*NK*D];      // [b*NK + j][d]
__device__ __half g_vt [B*D*NK];      // [b*D + n][j]  (transposed V)
__device__ __half g_attnh[MS*NK];     // fp16 attn
__device__ float g_slots[MS*D];
__device__ float g_upd  [MS*D];
__device__ float g_h    [MS*D];
__device__ float g_part [8*MS*D];     // = 4*MS*QKV3 floats (12.58 MB)

// ----------------------------------------------------------------------------
// HMMA / cp.async helpers (baseline PTX — compiles for plain compute_103)
// ----------------------------------------------------------------------------
__device__ __forceinline__ uint32_t smem_u32(const void* p) {
    uint32_t a;
    asm("{ .reg .u64 t; cvta.to.shared.u64 t, %1; cvt.u32.u64 %0, t; }"
        : "=r"(a) : "l"(p));
    return a;
}
#define LDSM_X4(r0, r1, r2, r3, addr) \
    asm volatile("ldmatrix.sync.aligned.m8n8.x4.shared.b16 {%0,%1,%2,%3}, [%4];" \
                 : "=r"(r0), "=r"(r1), "=r"(r2), "=r"(r3) : "r"(addr))
#define LDSM_X2(r0, r1, addr) \
    asm volatile("ldmatrix.sync.aligned.m8n8.x2.shared.b16 {%0,%1}, [%2];" \
                 : "=r"(r0), "=r"(r1) : "r"(addr))
#define MMA16816(c, a, b) \
    asm volatile("mma.sync.aligned.m16n8k16.row.col.f32.f16.f16.f32 " \
                 "{%0,%1,%2,%3}, {%4,%5,%6,%7}, {%8,%9}, {%0,%1,%2,%3};" \
                 : "+f"((c)[0]), "+f"((c)[1]), "+f"((c)[2]), "+f"((c)[3]) \
                 : "r"((a)[0]), "r"((a)[1]), "r"((a)[2]), "r"((a)[3]), \
                   "r"((b)[0]), "r"((b)[1]))
#define CP_ASYNC16(dst_u32, src_ptr) \
    asm volatile("cp.async.ca.shared.global [%0], [%1], 16;" \
                 :: "r"(dst_u32), "l"(src_ptr))
#define CP_COMMIT() asm volatile("cp.async.commit_group;" ::: "memory")
#define CP_WAIT(n)  asm volatile("cp.async.wait_group %0;" :: "n"(n) : "memory")

#define PITCH 40            // halves per smem row (80 B) — conflict-free ldmatrix
#define TILEH (128 * PITCH) // halves per 128-row tile
#define TILEB (TILEH * 2)   // bytes per tile
#define ATILEB (16 * PITCH * 2)  // bytes per 16-row A tile (1280)
#define TP 136              // transpose-tile pitch in halves

// ----------------------------------------------------------------------------
// Pure fp16 HMMA GEMM (C = A·B), split-K, 2-stage cp.async.
// ----------------------------------------------------------------------------
__global__ __launch_bounds__(256)
void hgemm_fp16(const __half* __restrict__ Ah, const __half* __restrict__ Bth,
                float* __restrict__ C, int M, int N, int K)
{
    extern __shared__ __align__(16) __half dyn[];
    int tid = threadIdx.x;
    int lane = tid & 31, wid = tid >> 5;
    int wm = wid >> 2, wn = wid & 3;
    int row0 = blockIdx.y * 128, col0 = blockIdx.x * 128;
    int kb   = K / gridDim.z;
    int kbeg = blockIdx.z * kb;
    float* Cz = C + (size_t)blockIdx.z * M * N;
    int nchunk = kb / 32;

    uint32_t base = smem_u32(dyn);

    float acc[4][4][4];
    #pragma unroll
    for (int mf = 0; mf < 4; mf++)
        #pragma unroll
        for (int nf = 0; nf < 4; nf++)
            #pragma unroll
            for (int e = 0; e < 4; e++) acc[mf][nf][e] = 0.f;

    int laneAr = lane & 15, laneAk = (lane & 16) ? 8 : 0;
    int laneBr = lane & 7,  laneBk = (lane & 8)  ? 8 : 0;

    auto load_stage = [&](int c, int s) {
        uint32_t sb = base + (uint32_t)s * 2 * TILEB;
        #pragma unroll
        for (int i = 0; i < 2; i++) {
            int idx = tid + i * 256;
            int row = idx >> 2, sg = idx & 3;
            size_t ga = (size_t)(row0 + row) * K + kbeg + c * 32 + sg * 8;
            size_t gb = (size_t)(col0 + row) * K + kbeg + c * 32 + sg * 8;
            uint32_t so = (uint32_t)(row * PITCH + sg * 8) * 2;
            CP_ASYNC16(sb + 0 * TILEB + so, Ah + ga);
            CP_ASYNC16(sb + 1 * TILEB + so, Bth + gb);
        }
    };

    load_stage(0, 0);
    CP_COMMIT();
    for (int c = 0; c < nchunk; c++) {
        int s = c & 1;
        if (c + 1 < nchunk) { load_stage(c + 1, s ^ 1); CP_COMMIT(); CP_WAIT(1); }
        else                { CP_WAIT(0); }
        __syncthreads();
        uint32_t bAh = base + (uint32_t)s * 2 * TILEB;
        uint32_t bBh = bAh + TILEB;
        #pragma unroll
        for (int ks = 0; ks < 32; ks += 16) {
            uint32_t bh[4][2];
            #pragma unroll
            for (int nf = 0; nf < 4; nf++) {
                uint32_t off = (uint32_t)((wn * 32 + nf * 8 + laneBr) * PITCH
                                          + ks + laneBk) * 2;
                LDSM_X2(bh[nf][0], bh[nf][1], bBh + off);
            }
            #pragma unroll
            for (int mf = 0; mf < 4; mf++) {
                uint32_t off = (uint32_t)((wm * 64 + mf * 16 + laneAr) * PITCH
                                          + ks + laneAk) * 2;
                uint32_t ah[4];
                LDSM_X4(ah[0], ah[1], ah[2], ah[3], bAh + off);
                #pragma unroll
                for (int nf = 0; nf < 4; nf++)
                    MMA16816(acc[mf][nf], ah, bh[nf]);
            }
        }
        __syncthreads();
    }
    #pragma unroll
    for (int mf = 0; mf < 4; mf++) {
        int r = row0 + wm * 64 + mf * 16 + (lane >> 2);
        #pragma unroll
        for (int nf = 0; nf < 4; nf++) {
            int c = col0 + wn * 32 + nf * 8 + (lane & 3) * 2;
            *(float2*)(Cz + (size_t)r * N + c) =
                make_float2(acc[mf][nf][0], acc[mf][nf][1]);
            *(float2*)(Cz + (size_t)(r + 8) * N + c) =
                make_float2(acc[mf][nf][2], acc[mf][nf][3]);
        }
    }
}
#define HG_SMEM (2 * 2 * TILEB)     // 40960

// ----------------------------------------------------------------------------
// Dual-output projection (K/V), pure fp16; K [row][n], V transposed [b*D+n][j];
// smem-staged coalesced epilogue.
// ----------------------------------------------------------------------------
__global__ __launch_bounds__(256)
void hgemm_dual(const __half* __restrict__ Ah,
                const __half* __restrict__ Bkh, const __half* __restrict__ Bvh,
                __half* __restrict__ Ck, __half* __restrict__ Cvt,
                int M, int N, int K)
{
    extern __shared__ __align__(16) __half dyn[];
    int tid = threadIdx.x;
    int lane = tid & 31, wid = tid >> 5;
    int wm = wid >> 2, wn = wid & 3;
    int row0 = blockIdx.y * 128, col0 = blockIdx.x * 128;
    int nchunk = K / 32;
    uint32_t base = smem_u32(dyn);

    float accK[4][4][4], accV[4][4][4];
    #pragma unroll
    for (int mf = 0; mf < 4; mf++)
        #pragma unroll
        for (int nf = 0; nf < 4; nf++)
            #pragma unroll
            for (int e = 0; e < 4; e++) { accK[mf][nf][e] = 0.f; accV[mf][nf][e] = 0.f; }

    int laneAr = lane & 15, laneAk = (lane & 16) ? 8 : 0;
    int laneBr = lane & 7,  laneBk = (lane & 8)  ? 8 : 0;

    auto load_stage = [&](int c, int s) {
        uint32_t sb = base + (uint32_t)s * 3 * TILEB;
        #pragma unroll
        for (int i = 0; i < 2; i++) {
            int idx = tid + i * 256;
            int row = idx >> 2, sg = idx & 3;
            size_t ga = (size_t)(row0 + row) * K + c * 32 + sg * 8;
            size_t gb = (size_t)(col0 + row) * K + c * 32 + sg * 8;
            uint32_t so = (uint32_t)(row * PITCH + sg * 8) * 2;
            CP_ASYNC16(sb + 0 * TILEB + so, Ah + ga);
            CP_ASYNC16(sb + 1 * TILEB + so, Bkh + gb);
            CP_ASYNC16(sb + 2 * TILEB + so, Bvh + gb);
        }
    };

    load_stage(0, 0);
    CP_COMMIT();
    for (int c = 0; c < nchunk; c++) {
        int s = c & 1;
        if (c + 1 < nchunk) { load_stage(c + 1, s ^ 1); CP_COMMIT(); CP_WAIT(1); }
        else                { CP_WAIT(0); }
        __syncthreads();
        uint32_t bAh = base + (uint32_t)s * 3 * TILEB;
        uint32_t bKh = bAh + TILEB;
        uint32_t bVh = bKh + TILEB;
        #pragma unroll
        for (int ks = 0; ks < 32; ks += 16) {
            uint32_t kh[4][2], vh[4][2];
            #pragma unroll
            for (int nf = 0; nf < 4; nf++) {
                uint32_t off = (uint32_t)((wn * 32 + nf * 8 + laneBr) * PITCH
                                          + ks + laneBk) * 2;
                LDSM_X2(kh[nf][0], kh[nf][1], bKh + off);
                LDSM_X2(vh[nf][0], vh[nf][1], bVh + off);
            }
            #pragma unroll
            for (int mf = 0; mf < 4; mf++) {
                uint32_t off = (uint32_t)((wm * 64 + mf * 16 + laneAr) * PITCH
                                          + ks + laneAk) * 2;
                uint32_t ah[4];
                LDSM_X4(ah[0], ah[1], ah[2], ah[3], bAh + off);
                #pragma unroll
                for (int nf = 0; nf < 4; nf++) {
                    MMA16816(accK[mf][nf], ah, kh[nf]);
                    MMA16816(accV[mf][nf], ah, vh[nf]);
                }
            }
        }
        __syncthreads();
    }

    // ---- epilogue via smem staging (coalesced stores) ----
    __half* tile = dyn;
    int bb = row0 >> 10, jbase = row0 & (NK - 1);

    #pragma unroll
    for (int mf = 0; mf < 4; mf++) {
        int rl = wm * 64 + mf * 16 + (lane >> 2);
        #pragma unroll
        for (int nf = 0; nf < 4; nf++) {
            int cl = wn * 32 + nf * 8 + (lane & 3) * 2;
            tile[(size_t)cl * TP + rl]           = __float2half_rn(accV[mf][nf][0]);
            tile[(size_t)(cl + 1) * TP + rl]     = __float2half_rn(accV[mf][nf][1]);
            tile[(size_t)cl * TP + rl + 8]       = __float2half_rn(accV[mf][nf][2]);
            tile[(size_t)(cl + 1) * TP + rl + 8] = __float2half_rn(accV[mf][nf][3]);
        }
    }
    __syncthreads();
    for (int idx = tid; idx < 128 * 16; idx += 256) {
        int n = idx >> 4, seg = idx & 15;
        uint4 v = *(const uint4*)&tile[(size_t)n * TP + seg * 8];
        *(uint4*)&Cvt[((size_t)bb * D + col0 + n) * NK + jbase + seg * 8] = v;
    }
    __syncthreads();

    #pragma unroll
    for (int mf = 0; mf < 4; mf++) {
        int rl = wm * 64 + mf * 16 + (lane >> 2);
        #pragma unroll
        for (int nf = 0; nf < 4; nf++) {
            int cl = wn * 32 + nf * 8 + (lane & 3) * 2;
            *(__half2*)&tile[(size_t)rl * TP + cl] =
                __floats2half2_rn(accK[mf][nf][0], accK[mf][nf][1]);
            *(__half2*)&tile[(size_t)(rl + 8) * TP + cl] =
                __floats2half2_rn(accK[mf][nf][2], accK[mf][nf][3]);
        }
    }
    __syncthreads();
    for (int idx = tid; idx < 128 * 16; idx += 256) {
        int r = idx >> 4, seg = idx & 15;
        uint4 v = *(const uint4*)&tile[(size_t)r * TP + seg * 8];
        *(uint4*)&Ck[(size_t)(row0 + r) * N + col0 + seg * 8] = v;
    }
}
#define DUAL_SMEM (2 * 3 * TILEB)   // 61440

// ----------------------------------------------------------------------------
// W1 + GLU fused, pure fp16, 2-stage pipelined; emits fp16 u*silu(g).
// ----------------------------------------------------------------------------
__global__ __launch_bounds__(256)
void hgemm_glu(const __half* __restrict__ Ah, const __half* __restrict__ W1th,
               __half* __restrict__ Ih, int M)
{
    extern __shared__ __align__(16) __half dyn[];
    int tid = threadIdx.x;
    int lane = tid & 31, wid = tid >> 5;
    int wm = wid >> 2, wn = wid & 3;
    int row0 = blockIdx.y * 128, col0 = blockIdx.x * 128;
    int nchunk = D / 32;
    uint32_t base = smem_u32(dyn);

    float accU[4][4][4], accG[4][4][4];
    #pragma unroll
    for (int mf = 0; mf < 4; mf++)
        #pragma unroll
        for (int nf = 0; nf < 4; nf++)
            #pragma unroll
            for (int e = 0; e < 4; e++) { accU[mf][nf][e] = 0.f; accG[mf][nf][e] = 0.f; }

    int laneAr = lane & 15, laneAk = (lane & 16) ? 8 : 0;
    int laneBr = lane & 7,  laneBk = (lane & 8)  ? 8 : 0;

    auto load_stage = [&](int c, int s) {
        uint32_t sb = base + (uint32_t)s * 3 * TILEB;
        #pragma unroll
        for (int i = 0; i < 2; i++) {
            int idx = tid + i * 256;
            int row = idx >> 2, sg = idx & 3;
            size_t ga = (size_t)(row0 + row) * D + c * 32 + sg * 8;
            size_t gu = (size_t)(col0 + row) * D + c * 32 + sg * 8;
            size_t gg = (size_t)(col0 + row + INNER) * D + c * 32 + sg * 8;
            uint32_t so = (uint32_t)(row * PITCH + sg * 8) * 2;
            CP_ASYNC16(sb + 0 * TILEB + so, Ah + ga);
            CP_ASYNC16(sb + 1 * TILEB + so, W1th + gu);
            CP_ASYNC16(sb + 2 * TILEB + so, W1th + gg);
        }
    };

    load_stage(0, 0);
    CP_COMMIT();
    for (int c = 0; c < nchunk; c++) {
        int s = c & 1;
        if (c + 1 < nchunk) { load_stage(c + 1, s ^ 1); CP_COMMIT(); CP_WAIT(1); }
        else                { CP_WAIT(0); }
        __syncthreads();
        uint32_t bAh = base + (uint32_t)s * 3 * TILEB;
        uint32_t bUh = bAh + TILEB;
        uint32_t bGh = bUh + TILEB;
        #pragma unroll
        for (int ks = 0; ks < 32; ks += 16) {
            uint32_t uh[4][2], gh[4][2];
            #pragma unroll
            for (int nf = 0; nf < 4; nf++) {
                uint32_t off = (uint32_t)((wn * 32 + nf * 8 + laneBr) * PITCH
                                          + ks + laneBk) * 2;
                LDSM_X2(uh[nf][0], uh[nf][1], bUh + off);
                LDSM_X2(gh[nf][0], gh[nf][1], bGh + off);
            }
            #pragma unroll
            for (int mf = 0; mf < 4; mf++) {
                uint32_t off = (uint32_t)((wm * 64 + mf * 16 + laneAr) * PITCH
                                          + ks + laneAk) * 2;
                uint32_t ah[4];
                LDSM_X4(ah[0], ah[1], ah[2], ah[3], bAh + off);
                #pragma unroll
                for (int nf = 0; nf < 4; nf++) {
                    MMA16816(accU[mf][nf], ah, uh[nf]);
                    MMA16816(accG[mf][nf], ah, gh[nf]);
                }
            }
        }
        __syncthreads();
    }
    #pragma unroll
    for (int mf = 0; mf < 4; mf++) {
        int r = row0 + wm * 64 + mf * 16 + (lane >> 2);
        #pragma unroll
        for (int nf = 0; nf < 4; nf++) {
            int c = col0 + wn * 32 + nf * 8 + (lane & 3) * 2;
            #pragma unroll
            for (int half_ = 0; half_ < 2; half_++) {
                int rr = r + half_ * 8;
                float u0 = accU[mf][nf][half_ * 2], u1 = accU[mf][nf][half_ * 2 + 1];
                float g0 = accG[mf][nf][half_ * 2], g1 = accG[mf][nf][half_ * 2 + 1];
                float v0 = u0 * (g0 / (1.f + expf(-g0)));
                float v1 = u1 * (g1 / (1.f + expf(-g1)));
                *(__half2*)(Ih + (size_t)rr * INNER + c) = __floats2half2_rn(v0, v1);
            }
        }
    }
}
#define GLU_SMEM (2 * 3 * TILEB)    // 61440

// ----------------------------------------------------------------------------
// dots + softmax, HMMA; 8 Wq split-K partials summed once into a persistent
// fp16 q smem tile (under the first K cp.asyncs). Emits fp16 attn.
// ----------------------------------------------------------------------------
#define QP 776                        // q smem pitch (halves)
#define DOTS_Q_BYTES (16 * QP * 2)    // 24832
#define DOTS_SMEM (DOTS_Q_BYTES + 2 * TILEB)   // 45312
__global__ __launch_bounds__(256)
void dots_hmma(const float* __restrict__ Qpart, const __half* __restrict__ Kb,
               __half* __restrict__ attnh)
{
    extern __shared__ __align__(16) __half dyn[];
    __half* qs = dyn;
    uint32_t qbase = smem_u32(qs);
    uint32_t kbase = qbase + DOTS_Q_BYTES;
    int tid = threadIdx.x;
    int lane = tid & 31, wn = tid >> 5;
    int b = blockIdx.y, j0 = blockIdx.x * 128;
    int nchunk = D / 32;                    // 24

    int laneAr = lane & 15, laneAk = (lane & 16) ? 8 : 0;
    int laneBr = lane & 7,  laneBk = (lane & 8)  ? 8 : 0;

    auto load_stage = [&](int c, int s) {
        uint32_t sb = kbase + (uint32_t)s * TILEB;
        #pragma unroll
        for (int i = 0; i < 2; i++) {
            int idx = tid + i * 256;
            int row = idx >> 2, sg = idx & 3;
            size_t gb = ((size_t)b * NK + j0 + row) * D + c * 32 + sg * 8;
            CP_ASYNC16(sb + (uint32_t)(row * PITCH + sg * 8) * 2, Kb + gb);
        }
    };

    load_stage(0, 0);
    CP_COMMIT();
    load_stage(1, 1);
    CP_COMMIT();

    // sum 8 Wq partials -> fp16 q (overlaps with the K cp.asyncs above)
    #pragma unroll
    for (int k = 0; k < 12; k++) {
        int idx4 = tid + k * 256;
        int row = idx4 / 192, col = (idx4 % 192) * 4;
        size_t o = ((size_t)b * S + row) * D + col;
        float4 v = *(const float4*)&Qpart[o];
        #pragma unroll
        for (int sp = 1; sp < 8; sp++) {
            float4 w = *(const float4*)&Qpart[(size_t)sp * MS * D + o];
            v.x += w.x; v.y += w.y; v.z += w.z; v.w += w.w;
        }
        *(__half2*)&qs[row * QP + col]     = __floats2half2_rn(v.x, v.y);
        *(__half2*)&qs[row * QP + col + 2] = __floats2half2_rn(v.z, v.w);
    }

    float acc[2][4];
    #pragma unroll
    for (int nf = 0; nf < 2; nf++)
        #pragma unroll
        for (int e = 0; e < 4; e++) acc[nf][e] = 0.f;

    for (int c = 0; c < nchunk; c++) {
        int s = c & 1;
        if (c + 2 < nchunk) { CP_WAIT(1); }
        else                { CP_WAIT(0); }
        __syncthreads();
        uint32_t bB = kbase + (uint32_t)s * TILEB;
        #pragma unroll
        for (int ks = 0; ks < 32; ks += 16) {
            uint32_t ah[4];
            LDSM_X4(ah[0], ah[1], ah[2], ah[3],
                    qbase + (uint32_t)(laneAr * QP + c * 32 + ks + laneAk) * 2);
            #pragma unroll
            for (int nf = 0; nf < 2; nf++) {
                uint32_t bh[2];
                LDSM_X2(bh[0], bh[1],
                        bB + (uint32_t)((wn * 16 + nf * 8 + laneBr) * PITCH
                                        + ks + laneBk) * 2);
                MMA16816(acc[nf], ah, bh);
            }
        }
        __syncthreads();
        if (c + 2 < nchunk) { load_stage(c + 2, s); CP_COMMIT(); }
    }

    // softmax over slot axis in registers
    int r = lane >> 2;
    #pragma unroll
    for (int nf = 0; nf < 2; nf++) {
        float s0 = acc[nf][0] * kSCALE, s1 = acc[nf][1] * kSCALE;
        float s2 = acc[nf][2] * kSCALE, s3 = acc[nf][3] * kSCALE;
        float m0 = fmaxf(s0, s2), m1 = fmaxf(s1, s3);
        #pragma unroll
        for (int o = 4; o <= 16; o <<= 1) {
            m0 = fmaxf(m0, __shfl_xor_sync(0xffffffffu, m0, o));
            m1 = fmaxf(m1, __shfl_xor_sync(0xffffffffu, m1, o));
        }
        float e0 = expf(s0 - m0), e1 = expf(s1 - m1);
        float e2 = expf(s2 - m0), e3 = expf(s3 - m1);
        float t0 = e0 + e2, t1 = e1 + e3;
        #pragma unroll
        for (int o = 4; o <= 16; o <<= 1) {
            t0 += __shfl_xor_sync(0xffffffffu, t0, o);
            t1 += __shfl_xor_sync(0xffffffffu, t1, o);
        }
        float a0 = e0 / t0 + 1e-8f, a1 = e1 / t1 + 1e-8f;
        float a2 = e2 / t0 + 1e-8f, a3 = e3 / t1 + 1e-8f;
        int col = j0 + wn * 16 + nf * 8 + (lane & 3) * 2;
        size_t o0 = ((size_t)b * S + r) * NK + col;
        size_t o1 = ((size_t)b * S + r + 8) * NK + col;
        *(__half2*)(attnh + o0) = __floats2half2_rn(a0, a1);
        *(__half2*)(attnh + o1) = __floats2half2_rn(a2, a3);
    }
}

// ----------------------------------------------------------------------------
// updates, HMMA: A = attn fp16 [16xNK], B = Vt rows; row sums via all-ones
// fragment; upd = (attn @ V) / rowsum.
// ----------------------------------------------------------------------------
#define UPD_STAGE (ATILEB + TILEB)
#define UPD_SMEM (2 * UPD_STAGE)     // 23040
__global__ __launch_bounds__(256)
void updates_hmma(const __half* __restrict__ Ath, const __half* __restrict__ Vt,
                  float* __restrict__ upd)
{
    extern __shared__ __align__(16) __half dyn[];
    int tid = threadIdx.x;
    int lane = tid & 31, wn = tid >> 5;
    int b = blockIdx.y, n0 = blockIdx.x * 128;
    uint32_t base = smem_u32(dyn);
    int nchunk = NK / 32;                   // 32

    float acc[2][4];
    float accS[4] = {0.f, 0.f, 0.f, 0.f};
    #pragma unroll
    for (int nf = 0; nf < 2; nf++)
        #pragma unroll
        for (int e = 0; e < 4; e++) acc[nf][e] = 0.f;

    int laneAr = lane & 15, laneAk = (lane & 16) ? 8 : 0;
    int laneBr = lane & 7,  laneBk = (lane & 8)  ? 8 : 0;
    uint32_t ones[2] = {0x3C003C00u, 0x3C003C00u};

    auto load_stage = [&](int c, int s) {
        uint32_t sb = base + (uint32_t)s * UPD_STAGE;
        if (tid < 64) {
            int row = tid >> 2, sg = tid & 3;
            size_t ga = ((size_t)b * S + row) * NK + c * 32 + sg * 8;
            CP_ASYNC16(sb + (uint32_t)(row * PITCH + sg * 8) * 2, Ath + ga);
        }
        #pragma unroll
        for (int i = 0; i < 2; i++) {
            int idx = tid + i * 256;
            int row = idx >> 2, sg = idx & 3;
            size_t gb = ((size_t)b * D + n0 + row) * NK + c * 32 + sg * 8;
            CP_ASYNC16(sb + ATILEB + (uint32_t)(row * PITCH + sg * 8) * 2, Vt + gb);
        }
    };

    load_stage(0, 0);
    CP_COMMIT();
    for (int c = 0; c < nchunk; c++) {
        int s = c & 1;
        if (c + 1 < nchunk) { load_stage(c + 1, s ^ 1); CP_COMMIT(); CP_WAIT(1); }
        else                { CP_WAIT(0); }
        __syncthreads();
        uint32_t bA = base + (uint32_t)s * UPD_STAGE;
        uint32_t bB = bA + ATILEB;
        #pragma unroll
        for (int ks = 0; ks < 32; ks += 16) {
            uint32_t ah[4];
            LDSM_X4(ah[0], ah[1], ah[2], ah[3],
                    bA + (uint32_t)(laneAr * PITCH + ks + laneAk) * 2);
            MMA16816(accS, ah, ones);
            #pragma unroll
            for (int nf = 0; nf < 2; nf++) {
                uint32_t bh[2];
                LDSM_X2(bh[0], bh[1],
                        bB + (uint32_t)((wn * 16 + nf * 8 + laneBr) * PITCH
                                        + ks + laneBk) * 2);
                MMA16816(acc[nf], ah, bh);
            }
        }
        __syncthreads();
    }

    int r = lane >> 2;
    float inv0 = 1.f / accS[0];
    float inv1 = 1.f / accS[2];
    #pragma unroll
    for (int nf = 0; nf < 2; nf++) {
        int col = n0 + wn * 16 + nf * 8 + (lane & 3) * 2;
        *(float2*)(upd + ((size_t)b * S + r) * D + col) =
            make_float2(acc[nf][0] * inv0, acc[nf][1] * inv0);
        *(float2*)(upd + ((size_t)b * S + r + 8) * D + col) =
            make_float2(acc[nf][2] * inv1, acc[nf][3] * inv1);
    }
}

// ----------------------------------------------------------------------------
// LN reduction helper (256 threads over D=768)
// ----------------------------------------------------------------------------
__device__ __forceinline__ void ln_stats(float v0, float v1, float v2,
                                         float* sa, float* sb2,
                                         float& mean, float& rinv)
{
    float s = v0 + v1 + v2;
    float q = v0 * v0 + v1 * v1 + v2 * v2;
    int tid = threadIdx.x;
    #pragma unroll
    for (int o = 16; o > 0; o >>= 1) {
        s += __shfl_down_sync(0xffffffffu, s, o);
        q += __shfl_down_sync(0xffffffffu, q, o);
    }
    int w = tid >> 5, l = tid & 31;
    if (l == 0) { sa[w] = s; sb2[w] = q; }
    __syncthreads();
    if (tid == 0) {
        float ts = 0.f, tq = 0.f;
        #pragma unroll
        for (int k = 0; k < 8; k++) { ts += sa[k]; tq += sb2[k]; }
        sa[0] = ts; sb2[0] = tq;
    }
    __syncthreads();
    mean = sa[0] * (1.0f / D);
    float var = sb2[0] * (1.0f / D) - mean * mean;
    rinv = rsqrtf(var + 1e-5f);
    __syncthreads();
}

__global__ __launch_bounds__(256)
void ln_h_kernel(const float* __restrict__ in, __half* __restrict__ oh,
                 const float* __restrict__ gamma, const float* __restrict__ beta)
{
    int row = blockIdx.x, tid = threadIdx.x;
    const float* x = in + (size_t)row * D;
    float v[3] = {x[tid], x[tid + 256], x[tid + 512]};
    __shared__ float sa[8], sb2[8];
    float mean, r;
    ln_stats(v[0], v[1], v[2], sa, sb2, mean, r);
    #pragma unroll
    for (int e = 0; e < 3; e++) {
        int idx = tid + e * 256;
        float y = (v[e] - mean) * r * gamma[idx] + beta[idx];
        oh[(size_t)row * D + idx] = __float2half_rn(y);
    }
}

__global__ __launch_bounds__(256)
void ln_dual_kernel(const float* __restrict__ slots, const float* __restrict__ upd,
                    float* __restrict__ hb,
                    const float* __restrict__ g1, const float* __restrict__ b1,
                    const float* __restrict__ g2, const float* __restrict__ b2,
                    __half* __restrict__ oh)
{
    int row = blockIdx.x, tid = threadIdx.x;
    const float* xs = slots + (size_t)row * D;
    const float* xu = upd + (size_t)row * D;
    float v[3];
    #pragma unroll
    for (int e = 0; e < 3; e++) v[e] = xs[tid + e * 256] + xu[tid + e * 256];
    __shared__ float sa[8], sb2[8];
    float mean, r;
    ln_stats(v[0], v[1], v[2], sa, sb2, mean, r);
    float y[3];
    #pragma unroll
    for (int e = 0; e < 3; e++) {
        int idx = tid + e * 256;
        y[e] = (v[e] - mean) * r * g1[idx] + b1[idx];
        hb[(size_t)row * D + idx] = y[e];
    }
    float mean2, r2;
    ln_stats(y[0], y[1], y[2], sa, sb2, mean2, r2);
    #pragma unroll
    for (int e = 0; e < 3; e++) {
        int idx = tid + e * 256;
        float z = (y[e] - mean2) * r2 * g2[idx] + b2[idx];
        oh[(size_t)row * D + idx] = __float2half_rn(z);
    }
}

// h = res + sum_{sp<8} part[sp]; res <- h; LN(h) -> oh(fp16)
__global__ __launch_bounds__(256)
void ln_red_kernel(const float* __restrict__ part, float* __restrict__ res,
                   const float* __restrict__ gamma, const float* __restrict__ beta,
                   __half* __restrict__ oh)
{
    int row = blockIdx.x, tid = threadIdx.x;
    float v[3];
    #pragma unroll
    for (int e = 0; e < 3; e++) {
        int idx = tid + e * 256;
        size_t o = (size_t)row * D + idx;
        float s = res[o];
        #pragma unroll
        for (int sp = 0; sp < 8; sp++) s += part[(size_t)sp * MS * D + o];
        v[e] = s;
        res[o] = s;
    }
    __shared__ float sa[8], sb2[8];
    float mean, r;
    ln_stats(v[0], v[1], v[2], sa, sb2, mean, r);
    #pragma unroll
    for (int e = 0; e < 3; e++) {
        int idx = tid + e * 256;
        float y = (v[e] - mean) * r * gamma[idx] + beta[idx];
        oh[(size_t)row * D + idx] = __float2half_rn(y);
    }
}

// h = res + sum_{sp<8} part[sp]; slots = LN_f(h); LN_s(slots) -> qn(fp16)
__global__ __launch_bounds__(256)
void ln_red_dual_kernel(const float* __restrict__ part, const float* __restrict__ res,
                        float* __restrict__ slots,
                        const float* __restrict__ gf, const float* __restrict__ bf,
                        const float* __restrict__ gs, const float* __restrict__ bs,
                        __half* __restrict__ qh)
{
    int row = blockIdx.x, tid = threadIdx.x;
    float v[3];
    #pragma unroll
    for (int e = 0; e < 3; e++) {
        int idx = tid + e * 256;
        size_t o = (size_t)row * D + idx;
        float s = res[o];
        #pragma unroll
        for (int sp = 0; sp < 8; sp++) s += part[(size_t)sp * MS * D + o];
        v[e] = s;
    }
    __shared__ float sa[8], sb2[8];
    float mean, r;
    ln_stats(v[0], v[1], v[2], sa, sb2, mean, r);
    float y[3];
    #pragma unroll
    for (int e = 0; e < 3; e++) {
        int idx = tid + e * 256;
        y[e] = (v[e] - mean) * r * gf[idx] + bf[idx];
        slots[(size_t)row * D + idx] = y[e];
    }
    float mean2, r2;
    ln_stats(y[0], y[1], y[2], sa, sb2, mean2, r2);
    #pragma unroll
    for (int e = 0; e < 3; e++) {
        int idx = tid + e * 256;
        float z = (y[e] - mean2) * r2 * gs[idx] + bs[idx];
        qh[(size_t)row * D + idx] = __float2half_rn(z);
    }
}

__global__ __launch_bounds__(256)
void wsplit_kernel(const float* __restrict__ W,
                   __half* __restrict__ Th,
                   int Krows, int Ncols, int n_off)
{
    __shared__ float tile[32][33];
    int n0 = blockIdx.x * 32, k0 = blockIdx.y * 32;
    int t = threadIdx.x;
    int tx = t & 31, ty = t >> 5;
    #pragma unroll
    for (int i = 0; i < 4; i++)
        tile[ty + i * 8][tx] = W[(size_t)(k0 + ty + i * 8) * Ncols + n0 + tx];
    __syncthreads();
    #pragma unroll
    for (int i = 0; i < 4; i++) {
        int n = n_off + n0 + ty + i * 8;
        Th[(size_t)n * Krows + k0 + tx] = __float2half_rn(tile[tx][ty + i * 8]);
    }
}

__global__ void init_slots_kernel(const float* __restrict__ noise,
                                  const float* __restrict__ mu,
                                  const float* __restrict__ ls,
                                  float* __restrict__ slots)
{
    int t = blockIdx.x * blockDim.x + threadIdx.x;
    if (t >= MS * D) return;
    int d = t % D;
    slots[t] = mu[d] + expf(ls[d]) * noise[t];
}

// encoder self-attention; reads 4 QKV split-K partials; emits fp16 O
__global__ __launch_bounds__(256)
void enc_attn_kernel(const float* __restrict__ QKVpart, __half* __restrict__ Oh)
{
    int b = blockIdx.x >> 3, h = blockIdx.x & 7;
    __shared__ float qs[16][65], ks[16][65], vs[16][65];
    __shared__ float p[16][17];
    int tid = threadIdx.x;
    int i = tid >> 4, jj = tid & 15;
    {
        int r = tid >> 4, c = (tid & 15) * 4;
        size_t base = ((size_t)b * S + r) * QKV3 + h * DH + c;
        float4 vq = *(const float4*)&QKVpart[base];
        float4 vk = *(const float4*)&QKVpart[base + HD];
        float4 vv = *(const float4*)&QKVpart[base + 2 * HD];
        #pragma unroll
        for (int sp = 1; sp < 4; sp++) {
            size_t o = (size_t)sp * MS * QKV3 + base;
            float4 w;
            w = *(const float4*)&QKVpart[o];
            vq.x += w.x; vq.y += w.y; vq.z += w.z; vq.w += w.w;
            w = *(const float4*)&QKVpart[o + HD];
            vk.x += w.x; vk.y += w.y; vk.z += w.z; vk.w += w.w;
            w = *(const float4*)&QKVpart[o + 2 * HD];
            vv.x += w.x; vv.y += w.y; vv.z += w.z; vv.w += w.w;
        }
        qs[r][c] = vq.x; qs[r][c+1] = vq.y; qs[r][c+2] = vq.z; qs[r][c+3] = vq.w;
        ks[r][c] = vk.x; ks[r][c+1] = vk.y; ks[r][c+2] = vk.z; ks[r][c+3] = vk.w;
        vs[r][c] = vv.x; vs[r][c+1] = vv.y; vs[r][c+2] = vv.z; vs[r][c+3] = vv.w;
    }
    __syncthreads();
    float s = 0.f;
    #pragma unroll
    for (int d = 0; d < DH; d++) s += qs[i][d] * ks[jj][d];
    s *= 0.125f;
    p[i][jj] = s;
    __syncthreads();
    float m = -1e30f;
    #pragma unroll
    for (int t2 = 0; t2 < 16; t2++) m = fmaxf(m, p[i][t2]);
    __syncthreads();
    float e = expf(s - m);
    p[i][jj] = e;
    __syncthreads();
    float sum = 0.f;
    #pragma unroll
    for (int t2 = 0; t2 < 16; t2++) sum += p[i][t2];
    __syncthreads();
    p[i][jj] = e / sum;
    __syncthreads();
    int io = tid >> 4, dbase = (tid & 15) * 4;
    float o[4] = {0.f, 0.f, 0.f, 0.f};
    #pragma unroll
    for (int t2 = 0; t2 < 16; t2++) {
        float pp = p[io][t2];
        o[0] += pp * vs[t2][dbase + 0];
        o[1] += pp * vs[t2][dbase + 1];
        o[2] += pp * vs[t2][dbase + 2];
        o[3] += pp * vs[t2][dbase + 3];
    }
    size_t base = ((size_t)b * S + io) * HD + h * DH + dbase;
    *(__half2*)(Oh + base)     = __floats2half2_rn(o[0], o[1]);
    *(__half2*)(Oh + base + 2) = __floats2half2_rn(o[2], o[3]);
}

// output map from fp16 attn: per (b,i) row — sum keys, write out[b][j][i]
__global__ __launch_bounds__(256)
void attn_out_kernel(const __half* __restrict__ attnh, float* __restrict__ out)
{
    int row = blockIdx.x;            // b*S + i
    int b = row >> 4, i = row & 15;
    const __half2* p = (const __half2*)(attnh + (size_t)row * NK);
    int tid = threadIdx.x;
    float2 v0 = __half22float2(p[tid * 2]);
    float2 v1 = __half22float2(p[tid * 2 + 1]);
    float s = v0.x + v0.y + v1.x + v1.y;
    __shared__ float sa[8];
    #pragma unroll
    for (int o = 16; o > 0; o >>= 1) s += __shfl_down_sync(0xffffffffu, s, o);
    int w = tid >> 5, l = tid & 31;
    if (l == 0) sa[w] = s;
    __syncthreads();
    if (tid == 0) {
        float ts = 0.f;
        #pragma unroll
        for (int k = 0; k < 8; k++) ts += sa[k];
        sa[0] = ts;
    }
    __syncthreads();
    float inv = 1.f / sa[0];
    size_t ob = (size_t)b * NK * S + i;
    int j = tid * 4;
    out[ob + (size_t)(j + 0) * S] = v0.x * inv;
    out[ob + (size_t)(j + 1) * S] = v0.y * inv;
    out[ob + (size_t)(j + 2) * S] = v1.x * inv;
    out[ob + (size_t)(j + 3) * S] = v1.y * inv;
}

// ----------------------------------------------------------------------------
// Host orchestration
// ----------------------------------------------------------------------------
extern "C" void kernel_launch(void* const* d_in, const int* in_sizes, int n_in,
                              void* d_out, int out_size)
{
    const float* x       = (const float*)d_in[0];
    const float* noise   = (const float*)d_in[1];
    const float* init_mu = (const float*)d_in[2];
    const float* init_ls = (const float*)d_in[3];
    const float* Wk      = (const float*)d_in[4];
    const float* Wv      = (const float*)d_in[5];
    const float* Wq      = (const float*)d_in[6];
    const float* ni_g    = (const float*)d_in[7];
    const float* ni_b    = (const float*)d_in[8];
    const float* ns_g    = (const float*)d_in[9];
    const float* ns_b    = (const float*)d_in[10];
    const float* nica_g  = (const float*)d_in[11];
    const float* nica_b  = (const float*)d_in[12];
    const float* ln1_g   = (const float*)d_in[13];
    const float* ln1_b   = (const float*)d_in[14];
    const float* Wq_a    = (const float*)d_in[15];
    const float* Wk_a    = (const float*)d_in[16];
    const float* Wv_a    = (const float*)d_in[17];
    const float* Wo_a    = (const float*)d_in[18];
    const float* ln2_g   = (const float*)d_in[19];
    const float* ln2_b   = (const float*)d_in[20];
    const float* W1      = (const float*)d_in[21];
    const float* W2      = (const float*)d_in[22];
    const float* lnf_g   = (const float*)d_in[23];
    const float* lnf_b   = (const float*)d_in[24];

    __half *xnh, *wkh, *wvh, *wqh, *wqkh, *woh, *w1h, *w2h;
    __half *qnh, *abh, *fbh, *innh, *oah, *kb, *vt, *attnh;
    float *slots, *upd, *hb, *part;
    cudaGetSymbolAddress((void**)&xnh,  g_xnh);
    cudaGetSymbolAddress((void**)&wkh,  g_wkh);
    cudaGetSymbolAddress((void**)&wvh,  g_wvh);
    cudaGetSymbolAddress((void**)&wqh,  g_wqh);
    cudaGetSymbolAddress((void**)&wqkh, g_wqkh);
    cudaGetSymbolAddress((void**)&woh,  g_woh);
    cudaGetSymbolAddress((void**)&w1h,  g_w1h);
    cudaGetSymbolAddress((void**)&w2h,  g_w2h);
    cudaGetSymbolAddress((void**)&qnh,  g_qnh);
    cudaGetSymbolAddress((void**)&abh,  g_abh);
    cudaGetSymbolAddress((void**)&fbh,  g_fbh);
    cudaGetSymbolAddress((void**)&innh, g_innh);
    cudaGetSymbolAddress((void**)&oah,  g_oah);
    cudaGetSymbolAddress((void**)&kb,   g_k);
    cudaGetSymbolAddress((void**)&vt,   g_vt);
    cudaGetSymbolAddress((void**)&attnh,g_attnh);
    cudaGetSymbolAddress((void**)&slots,g_slots);
    cudaGetSymbolAddress((void**)&upd,  g_upd);
    cudaGetSymbolAddress((void**)&hb,   g_h);
    cudaGetSymbolAddress((void**)&part, g_part);

    cudaFuncSetAttribute(hgemm_fp16, cudaFuncAttributeMaxDynamicSharedMemorySize, HG_SMEM);
    cudaFuncSetAttribute(hgemm_dual, cudaFuncAttributeMaxDynamicSharedMemorySize, DUAL_SMEM);
    cudaFuncSetAttribute(hgemm_glu,  cudaFuncAttributeMaxDynamicSharedMemorySize, GLU_SMEM);
    cudaFuncSetAttribute(dots_hmma,  cudaFuncAttributeMaxDynamicSharedMemorySize, DOTS_SMEM);
    cudaFuncSetAttribute(updates_hmma, cudaFuncAttributeMaxDynamicSharedMemorySize, UPD_SMEM);

    // ---- precompute ----
    wsplit_kernel<<<dim3(D / 32, D / 32), 256>>>(Wk, wkh, D, D, 0);
    wsplit_kernel<<<dim3(D / 32, D / 32), 256>>>(Wv, wvh, D, D, 0);
    ln_h_kernel<<<B * NK, 256>>>(x, xnh, ni_g, ni_b);
    init_slots_kernel<<<(MS * D + 255) / 256, 256>>>(noise, init_mu, init_ls, slots);
    wsplit_kernel<<<dim3(D / 32, D / 32), 256>>>(Wq, wqh, D, D, 0);
    hgemm_dual<<<dim3(D / 128, (B * NK) / 128), 256, DUAL_SMEM>>>(
        xnh, wkh, wvh, kb, vt, B * NK, D, D);
    wsplit_kernel<<<dim3(HD / 32, D / 32), 256>>>(Wq_a, wqkh, D, HD, 0);
    wsplit_kernel<<<dim3(HD / 32, D / 32), 256>>>(Wk_a, wqkh, D, HD, HD);
    wsplit_kernel<<<dim3(HD / 32, D / 32), 256>>>(Wv_a, wqkh, D, HD, 2 * HD);
    wsplit_kernel<<<dim3(D / 32, HD / 32), 256>>>(Wo_a, woh, HD, D, 0);
    wsplit_kernel<<<dim3((2 * INNER) / 32, D / 32), 256>>>(W1, w1h, D, 2 * INNER, 0);
    wsplit_kernel<<<dim3(D / 32, INNER / 32), 256>>>(W2, w2h, INNER, D, 0);
    ln_h_kernel<<<MS, 256>>>(slots, qnh, ns_g, ns_b);

    // ---- 4 slot-attention steps (11 launches each) ----
    for (int it = 0; it < N_STEPS; it++) {
        hgemm_fp16<<<dim3(D / 128, MS / 128, 8), 256, HG_SMEM>>>(qnh, wqh,
                                                                 part, MS, D, D);
        dots_hmma<<<dim3(NK / 128, B), 256, DOTS_SMEM>>>(part, kb, attnh);
        updates_hmma<<<dim3(D / 128, B), 256, UPD_SMEM>>>(attnh, vt, upd);
        ln_dual_kernel<<<MS, 256>>>(slots, upd, hb, nica_g, nica_b,
                                    ln1_g, ln1_b, abh);
        hgemm_fp16<<<dim3(QKV3 / 128, MS / 128, 4), 256, HG_SMEM>>>(abh, wqkh,
                                                                    part, MS, QKV3, D);
        enc_attn_kernel<<<B * H, 256>>>(part, oah);
        hgemm_fp16<<<dim3(D / 128, MS / 128, 8), 256, HG_SMEM>>>(oah, woh,
                                                                 part, MS, D, HD);
        ln_red_kernel<<<MS, 256>>>(part, hb, ln2_g, ln2_b, fbh);
        hgemm_glu<<<dim3(INNER / 128, MS / 128), 256, GLU_SMEM>>>(fbh, w1h,
                                                                  innh, MS);
        hgemm_fp16<<<dim3(D / 128, MS / 128, 8), 256, HG_SMEM>>>(innh, w2h,
                                                                 part, MS, D, INNER);
        ln_red_dual_kernel<<<MS, 256>>>(part, hb, slots, lnf_g, lnf_b,
                                        ns_g, ns_b, qnh);
    }

    // ---- outputs: slots [32,16,768], then attn_map [32,1024,16] ----
    float* out = (float*)d_out;
    cudaMemcpyAsync(out, slots, (size_t)MS * D * sizeof(float),
                    cudaMemcpyDeviceToDevice);
    attn_out_kernel<<<MS, 256>>>(attnh, out + (size_t)MS * D);
}